// round 7
// baseline (speedup 1.0000x reference)
#include <cuda_runtime.h>
#include <cstdint>

#define BATCH   32
#define SEQLEN  4096
#define CIN     7
#define OUTC    512
#define NKERN   74
#define TB      128                  // timesteps per block
#define NT      256                  // threads per block (1 output pair each)
#define T       16                   // output timesteps per accumulator chunk
#define SROWS   (TB + 24)            // smem rows: t0-22 .. t0+TB+1  (152, even)
#define NCOMBO  11                   // distinct (cA,cB) channel pairs
#define GP      ((T + 24) / 2)       // 20 row-pairs per chunk

// ---------- packed f32x2 helpers ----------
__device__ __forceinline__ unsigned long long pack2(float lo, float hi) {
    unsigned long long r;
    asm("mov.b64 %0, {%1, %2};" : "=l"(r) : "f"(lo), "f"(hi));
    return r;
}
__device__ __forceinline__ void fma2(unsigned long long& acc,
                                     unsigned long long a, unsigned long long b) {
    asm("fma.rn.f32x2 %0, %1, %2, %0;" : "+l"(acc) : "l"(a), "l"(b));
}

// Dense 24-tap FIR: out[b,t,o] = sum_{d=0}^{23} W[o,d] * x[b, t+d-22, c(o)]
// tap d (offset o = d-22) maps to kernel (i,j): i = (1-o)/3, j = o+1+3i.

__global__ __launch_bounds__(NT, 2)
void conv_main(const float* __restrict__ x, const float* __restrict__ kern,
               float* __restrict__ out) {
    __shared__ float xs[CIN][SROWS];
    __shared__ __align__(16) float2 pk[NCOMBO][SROWS];   // packed (xA,xB) per combo
    __shared__ float ks[NKERN * 24];

    const int nt_tiles = SEQLEN / TB;        // 32
    const int b   = blockIdx.x / nt_tiles;
    const int t0  = (blockIdx.x % nt_tiles) * TB;
    const int tid = threadIdx.x;

    // ---- phase 1: raw x window + kernel weights into smem ----
    {
        const float* xb = x + (size_t)b * SEQLEN * CIN;
        for (int idx = tid; idx < CIN * SROWS; idx += NT) {
            int r = idx / CIN;
            int c = idx % CIN;
            int g = t0 - 22 + r;
            float v = 0.0f;
            if (g >= 0 && g < SEQLEN) v = xb[(size_t)g * CIN + c];
            xs[c][r] = v;
        }
        for (int idx = tid; idx < NKERN * 24; idx += NT)
            ks[idx] = kern[idx];
    }
    __syncthreads();

    // ---- phase 2: build packed channel-pair arrays ----
    // combos 0..6: (c,c); 7:(0,1) 8:(2,3) 9:(4,5) 10:(6,0)
    for (int idx = tid; idx < NCOMBO * SROWS; idx += NT) {
        int cm = idx / SROWS, r = idx % SROWS;
        int ca, cb;
        if (cm < 7)       { ca = cm;           cb = cm; }
        else if (cm < 10) { ca = 2 * (cm - 7); cb = ca + 1; }
        else              { ca = 6;            cb = 0; }
        pk[cm][r] = make_float2(xs[ca][r], xs[cb][r]);
    }
    __syncthreads();

    // ---- this thread's output pair (o0 even -> aligned STG.64) ----
    const int o0 = 2 * tid;
    const int o1 = o0 + 1;
    const int cA = o0 / 73, kA = o0 % 73;
    int cB, kB;
    if (o1 == 511) { cB = 0; kB = 73; } else { cB = o1 / 73; kB = o1 % 73; }

    int combo;
    if (cA == cB)        combo = cA;
    else if (o1 == 511)  combo = 10;
    else                 combo = 7 + (cA >> 1);

    // ---- packed weight pairs in registers (48 regs) ----
    unsigned long long wreg[24];
#pragma unroll
    for (int d = 0; d < 24; d++) {
        const int o = d - 22;
        const int i = (1 - o) / 3;
        const int j = o + 1 + 3 * i;
        wreg[d] = pack2(ks[kA * 24 + i * 3 + j], ks[kB * 24 + i * 3 + j]);
    }

    // float4 view: element q holds packed rows (2q, 2q+1) of this combo stream
    const float4* pk4 = reinterpret_cast<const float4*>(pk[combo]);
    float* op = out + ((size_t)b * SEQLEN + t0) * OUTC + o0;

    // ---- streaming FIR with 1-deep LDS prefetch (incl. across chunks) ----
    float4 qcur = pk4[0];
#pragma unroll 1
    for (int cbase = 0; cbase < TB; cbase += T) {
        unsigned long long acc[T];
#pragma unroll
        for (int tr = 0; tr < T; tr++) acc[tr] = 0ull;

#pragma unroll
        for (int gp = 0; gp < GP; gp++) {
            // prefetch the NEXT row-pair before consuming the current one
            float4 qn;
            if (gp < GP - 1)          qn = pk4[(cbase >> 1) + gp + 1];
            else if (cbase + T < TB)  qn = pk4[(cbase + T) >> 1];

            const unsigned long long px0 = pack2(qcur.x, qcur.y);   // row 2*gp
            const unsigned long long px1 = pack2(qcur.z, qcur.w);   // row 2*gp+1
            const int gg = 2 * gp;
#pragma unroll
            for (int tr = 0; tr < T; tr++) {
                const int d0 = gg - tr;                       // compile-time
                if (d0 >= 0 && d0 < 24) fma2(acc[tr], px0, wreg[d0]);
                const int d1 = gg + 1 - tr;
                if (d1 >= 0 && d1 < 24) fma2(acc[tr], px1, wreg[d1]);
            }
            qcur = qn;
        }

#pragma unroll
        for (int tr = 0; tr < T; tr++)
            *reinterpret_cast<unsigned long long*>(op + (size_t)tr * OUTC) = acc[tr];
        op += (size_t)T * OUTC;
    }

    // ---- folded t = L-1 fix: right padding kills ALL j==2 taps there ----
    // Same thread re-stores its own pair -> program-ordered WAW, safe.
    if (t0 + TB == SEQLEN) {
        const int row = TB + 21;                  // local row of t = L-1
        float sA = 0.0f, sB = 0.0f;
#pragma unroll
        for (int i = 0; i < 8; i++) {
#pragma unroll
            for (int j = 0; j < 2; j++) {
                const int r = row + (j - 1) - 3 * i;
                const float2 v = pk[combo][r];
                sA += v.x * ks[kA * 24 + i * 3 + j];
                sB += v.y * ks[kB * 24 + i * 3 + j];
            }
        }
        *reinterpret_cast<unsigned long long*>(
            out + ((size_t)b * SEQLEN + (SEQLEN - 1)) * OUTC + o0) = pack2(sA, sB);
    }
}

extern "C" void kernel_launch(void* const* d_in, const int* in_sizes, int n_in,
                              void* d_out, int out_size) {
    const float* x    = (const float*)d_in[0];   // (32, 4096, 7) f32
    const float* kern = (const float*)d_in[1];   // (74, 8, 3)  f32
    float* out        = (float*)d_out;           // (32, 4096, 512) f32

    conv_main<<<BATCH * (SEQLEN / TB), NT>>>(x, kern, out);
}

// round 10
// speedup vs baseline: 1.0131x; 1.0131x over previous
#include <cuda_runtime.h>
#include <cstdint>

#define BATCH   32
#define SEQLEN  4096
#define CIN     7
#define OUTC    512
#define NKERN   74
#define TB      128                  // timesteps per block
#define NT      256                  // threads per block (1 output pair each)
#define T       16                   // output timesteps per accumulator chunk
#define SROWS   (TB + 24)            // 152 smem rows: t0-22 .. t0+TB+1
#define NCOMBO  11                   // distinct (cA,cB) channel pairs

// ---- dynamic smem layout (byte offsets) ----
#define SM_PK   0                            // float2 pk[11][152]      = 13376
#define SM_KS   (NCOMBO * SROWS * 8)         // float  ks[74*24]        = 7104
#define SM_U    (SM_KS + NKERN * 24 * 4)     // 20480: union xs[7][152] | wpk
#define SM_WPK  SM_U                         // float2 wpk[24][256]     = 49152
#define SMEM_TOTAL (SM_U + 24 * NT * 8)      // 69632

// ---------- packed f32x2 helpers ----------
__device__ __forceinline__ unsigned long long pack2(float lo, float hi) {
    unsigned long long r;
    asm("mov.b64 %0, {%1, %2};" : "=l"(r) : "f"(lo), "f"(hi));
    return r;
}
__device__ __forceinline__ void fma2(unsigned long long& acc,
                                     unsigned long long a, unsigned long long b) {
    asm("fma.rn.f32x2 %0, %1, %2, %0;" : "+l"(acc) : "l"(a), "l"(b));
}
__device__ __forceinline__ uint32_t smem_u32(const void* p) {
    uint32_t a;
    asm("{ .reg .u64 t; cvta.to.shared.u64 t, %1; cvt.u32.u64 %0, t; }" : "=r"(a) : "l"(p));
    return a;
}
// volatile: pins each pass's 12 weight loads in place (short live ranges)
__device__ __forceinline__ unsigned long long lds64v(uint32_t addr) {
    unsigned long long r;
    asm volatile("ld.volatile.shared.b64 %0, [%1];" : "=l"(r) : "r"(addr));
    return r;
}

// Dense 24-tap FIR: out[b,t,o] = sum_{d=0}^{23} W[o,d] * x[b, t+d-22, c(o)]
// tap d (offset o = d-22) maps to kernel (i,j): i = (1-o)/3, j = o+1+3i.
// j(d) == 2  <=>  d mod 3 == 2   (used by the t=L-1 fix).

__global__ __launch_bounds__(NT, 3)
void conv_main(const float* __restrict__ x, const float* __restrict__ kern,
               float* __restrict__ out) {
    extern __shared__ char smem[];
    float2* pk  = (float2*)(smem + SM_PK);    // [11][152] packed (xA,xB) per combo
    float*  ks  = (float*)(smem + SM_KS);     // [74*24]
    float*  xs  = (float*)(smem + SM_U);      // [7][152]  (union with wpk)
    float2* wpk = (float2*)(smem + SM_WPK);   // [24][256] per-thread packed weights
    const uint32_t sb = smem_u32(smem);

    const int nt_tiles = SEQLEN / TB;         // 32
    const int b   = blockIdx.x / nt_tiles;
    const int t0  = (blockIdx.x % nt_tiles) * TB;
    const int tid = threadIdx.x;

    // ---- phase 1: raw x window + kernel weights ----
    {
        const float* xb = x + (size_t)b * SEQLEN * CIN;
        for (int idx = tid; idx < CIN * SROWS; idx += NT) {
            int r = idx / CIN;
            int c = idx % CIN;
            int g = t0 - 22 + r;
            float v = 0.0f;
            if (g >= 0 && g < SEQLEN) v = xb[(size_t)g * CIN + c];
            xs[c * SROWS + r] = v;
        }
        for (int idx = tid; idx < NKERN * 24; idx += NT)
            ks[idx] = kern[idx];
    }
    __syncthreads();

    // ---- phase 2: packed channel-pair arrays ----
    // combos 0..6: (c,c); 7:(0,1) 8:(2,3) 9:(4,5) 10:(6,0)
    for (int idx = tid; idx < NCOMBO * SROWS; idx += NT) {
        int cm = idx / SROWS, r = idx % SROWS;
        int ca, cb;
        if (cm < 7)       { ca = cm;           cb = cm; }
        else if (cm < 10) { ca = 2 * (cm - 7); cb = ca + 1; }
        else              { ca = 6;            cb = 0; }
        pk[cm * SROWS + r] = make_float2(xs[ca * SROWS + r], xs[cb * SROWS + r]);
    }
    __syncthreads();     // last xs read is above; wpk may now overwrite xs

    // ---- this thread's output pair (o0 even -> aligned STG.64) ----
    const int o0 = 2 * tid;
    const int o1 = o0 + 1;
    const int cA = o0 / 73, kA = o0 % 73;
    int cB, kB;
    if (o1 == 511) { cB = 0; kB = 73; } else { cB = o1 / 73; kB = o1 % 73; }

    int combo;
    if (cA == cB)        combo = cA;
    else if (o1 == 511)  combo = 10;
    else                 combo = 7 + (cA >> 1);

    // ---- phase 3: per-thread packed weight table (own slots only; no sync) ----
#pragma unroll
    for (int d = 0; d < 24; d++) {
        const int o = d - 22;
        const int i = (1 - o) / 3;
        const int j = o + 1 + 3 * i;
        wpk[d * NT + tid] = make_float2(ks[kA * 24 + i * 3 + j],
                                        ks[kB * 24 + i * 3 + j]);
    }

    const float4* pk4 = (const float4*)(pk + combo * SROWS);  // 16B-aligned rows
    const uint32_t wbase = sb + SM_WPK + tid * 8;
    float* op = out + ((size_t)b * SEQLEN + t0) * OUTC + o0;

    // ---- streaming FIR: two 12-tap passes per chunk (halves weight reg pressure) ----
#pragma unroll 1
    for (int cbase = 0; cbase < TB; cbase += T) {
        unsigned long long acc[T];
#pragma unroll
        for (int tr = 0; tr < T; tr++) acc[tr] = 0ull;

        // pass 0: taps 0..11, rows 0..27 (q = 0..13)
        {
            unsigned long long wp[12];
#pragma unroll
            for (int k = 0; k < 12; k++) wp[k] = lds64v(wbase + k * (NT * 8));
#pragma unroll
            for (int q = 0; q <= 13; q++) {
                const float4 v = pk4[(cbase >> 1) + q];
                const unsigned long long px0 = pack2(v.x, v.y);
                const unsigned long long px1 = pack2(v.z, v.w);
#pragma unroll
                for (int tr = 0; tr < T; tr++) {
                    const int d0 = 2 * q - tr;
                    if (d0 >= 0 && d0 < 12) fma2(acc[tr], px0, wp[d0]);
                    const int d1 = 2 * q + 1 - tr;
                    if (d1 >= 0 && d1 < 12) fma2(acc[tr], px1, wp[d1]);
                }
            }
        }
        // pass 1: taps 12..23, rows 12..39 (q = 6..19)
        {
            unsigned long long wp[12];
#pragma unroll
            for (int k = 0; k < 12; k++) wp[k] = lds64v(wbase + (12 + k) * (NT * 8));
#pragma unroll
            for (int q = 6; q <= 19; q++) {
                const float4 v = pk4[(cbase >> 1) + q];
                const unsigned long long px0 = pack2(v.x, v.y);
                const unsigned long long px1 = pack2(v.z, v.w);
#pragma unroll
                for (int tr = 0; tr < T; tr++) {
                    const int d0 = 2 * q - tr;
                    if (d0 >= 12 && d0 < 24) fma2(acc[tr], px0, wp[d0 - 12]);
                    const int d1 = 2 * q + 1 - tr;
                    if (d1 >= 12 && d1 < 24) fma2(acc[tr], px1, wp[d1 - 12]);
                }
            }
        }

#pragma unroll
        for (int tr = 0; tr < T; tr++)
            *reinterpret_cast<unsigned long long*>(op + (size_t)tr * OUTC) = acc[tr];
        op += (size_t)T * OUTC;
    }

    // ---- folded t = L-1 fix: right padding drops all j==2 taps (d mod 3 == 2) ----
    // Same thread re-stores its own pair -> program-ordered WAW, safe.
    if (t0 + TB == SEQLEN) {
        float sA = 0.0f, sB = 0.0f;
#pragma unroll
        for (int d = 0; d < 24; d++) {
            if (d % 3 != 2) {
                const float2 w = wpk[d * NT + tid];
                const float2 v = pk[combo * SROWS + 127 + d];
                sA += v.x * w.x;
                sB += v.y * w.y;
            }
        }
        *reinterpret_cast<unsigned long long*>(
            out + ((size_t)b * SEQLEN + (SEQLEN - 1)) * OUTC + o0) = pack2(sA, sB);
    }
}

extern "C" void kernel_launch(void* const* d_in, const int* in_sizes, int n_in,
                              void* d_out, int out_size) {
    const float* x    = (const float*)d_in[0];   // (32, 4096, 7) f32
    const float* kern = (const float*)d_in[1];   // (74, 8, 3)  f32
    float* out        = (float*)d_out;           // (32, 4096, 512) f32

    cudaFuncSetAttribute(conv_main, cudaFuncAttributeMaxDynamicSharedMemorySize,
                         SMEM_TOTAL);
    conv_main<<<BATCH * (SEQLEN / TB), NT, SMEM_TOTAL>>>(x, kern, out);
}